// round 1
// baseline (speedup 1.0000x reference)
#include <cuda_runtime.h>
#include <math.h>

// Problem-fixed maxima (registry problem: N=100000, E=1600000)
#define N_MAX 100000
#define E_MAX 1600000

// Scratch (allocation-free rule: __device__ globals)
__device__ float g_deg[N_MAX];
__device__ float g_dinv[N_MAX];
__device__ __align__(16) float g_g1[N_MAX * 32];
__device__ __align__(16) float g_acc1[N_MAX * 32];
__device__ __align__(16) float g_g2[N_MAX * 16];
__device__ __align__(16) float g_acc2[N_MAX * 16];

// K1: deg[i] = 1 (self-loop)
__global__ void k_deg_init(int n) {
    int i = blockIdx.x * blockDim.x + threadIdx.x;
    if (i < n) g_deg[i] = 1.0f;
}

// K2: deg[dst] += 1 per edge
__global__ void k_deg_count(const int* __restrict__ dst, int e) {
    int j = blockIdx.x * blockDim.x + threadIdx.x;
    if (j < e) atomicAdd(&g_deg[dst[j]], 1.0f);
}

// K3: dinv = rsqrt(deg); g1 = (x @ W1) * dinv; acc1 = 0
__global__ void k_prep1(const float* __restrict__ x, const float* __restrict__ W1, int n) {
    __shared__ float sW[8 * 32];
    for (int t = threadIdx.x; t < 256; t += blockDim.x) sW[t] = W1[t];
    __syncthreads();
    int i = blockIdx.x * blockDim.x + threadIdx.x;
    if (i >= n) return;

    float4 xa = *reinterpret_cast<const float4*>(x + (size_t)i * 8);
    float4 xb = *reinterpret_cast<const float4*>(x + (size_t)i * 8 + 4);
    float xv[8] = {xa.x, xa.y, xa.z, xa.w, xb.x, xb.y, xb.z, xb.w};

    float di = rsqrtf(g_deg[i]);
    g_dinv[i] = di;

    float* g1r = g_g1 + (size_t)i * 32;
    float* a1r = g_acc1 + (size_t)i * 32;
#pragma unroll
    for (int f4 = 0; f4 < 8; f4++) {
        float4 hv;
        float* hp = &hv.x;
#pragma unroll
        for (int c = 0; c < 4; c++) {
            int f = f4 * 4 + c;
            float h = 0.f;
#pragma unroll
            for (int k = 0; k < 8; k++) h = fmaf(xv[k], sW[k * 32 + f], h);
            hp[c] = h * di;
        }
        reinterpret_cast<float4*>(g1r)[f4] = hv;
        reinterpret_cast<float4*>(a1r)[f4] = make_float4(0.f, 0.f, 0.f, 0.f);
    }
}

// K4/K6: acc[dst] += g[src]  (vector reductions, no return)
template <int F4, bool LAYER1>
__global__ void k_scatter(const int* __restrict__ src, const int* __restrict__ dst, int e) {
    int j = blockIdx.x * blockDim.x + threadIdx.x;
    if (j >= e) return;
    int s = src[j];
    int d = dst[j];
    const float4* gs = reinterpret_cast<const float4*>((LAYER1 ? g_g1 : g_g2) + (size_t)s * F4 * 4);
    float4* ad = reinterpret_cast<float4*>((LAYER1 ? g_acc1 : g_acc2) + (size_t)d * F4 * 4);
#pragma unroll
    for (int k = 0; k < F4; k++) {
        float4 v = __ldg(gs + k);
        asm volatile("red.global.add.v4.f32 [%0], {%1, %2, %3, %4};"
                     :: "l"(ad + k), "f"(v.x), "f"(v.y), "f"(v.z), "f"(v.w)
                     : "memory");
    }
}

// K5: h1 = relu(dinv*(acc1+g1) + b1); g2 = (h1 @ W2) * dinv; acc2 = 0
__global__ void k_mid(const float* __restrict__ W2, const float* __restrict__ b1, int n) {
    __shared__ float sW[32 * 16];
    __shared__ float sb[32];
    for (int t = threadIdx.x; t < 512; t += blockDim.x) sW[t] = W2[t];
    if (threadIdx.x < 32) sb[threadIdx.x] = b1[threadIdx.x];
    __syncthreads();
    int i = blockIdx.x * blockDim.x + threadIdx.x;
    if (i >= n) return;

    float di = g_dinv[i];
    const float* g1r = g_g1 + (size_t)i * 32;
    const float* a1r = g_acc1 + (size_t)i * 32;

    float h1[32];
#pragma unroll
    for (int f4 = 0; f4 < 8; f4++) {
        float4 a = reinterpret_cast<const float4*>(a1r)[f4];
        float4 g = reinterpret_cast<const float4*>(g1r)[f4];
        h1[f4 * 4 + 0] = fmaxf(di * (a.x + g.x) + sb[f4 * 4 + 0], 0.f);
        h1[f4 * 4 + 1] = fmaxf(di * (a.y + g.y) + sb[f4 * 4 + 1], 0.f);
        h1[f4 * 4 + 2] = fmaxf(di * (a.z + g.z) + sb[f4 * 4 + 2], 0.f);
        h1[f4 * 4 + 3] = fmaxf(di * (a.w + g.w) + sb[f4 * 4 + 3], 0.f);
    }

    float* g2r = g_g2 + (size_t)i * 16;
    float* a2r = g_acc2 + (size_t)i * 16;
#pragma unroll
    for (int f4 = 0; f4 < 4; f4++) {
        float4 hv;
        float* hp = &hv.x;
#pragma unroll
        for (int c = 0; c < 4; c++) {
            int f = f4 * 4 + c;
            float h = 0.f;
#pragma unroll
            for (int k = 0; k < 32; k++) h = fmaf(h1[k], sW[k * 16 + f], h);
            hp[c] = h * di;
        }
        reinterpret_cast<float4*>(g2r)[f4] = hv;
        reinterpret_cast<float4*>(a2r)[f4] = make_float4(0.f, 0.f, 0.f, 0.f);
    }
}

// K7: h2 = relu(dinv*(acc2+g2) + b2); out = sigmoid(h2 @ Wfc + bfc)
__global__ void k_final(const float* __restrict__ b2, const float* __restrict__ Wfc,
                        const float* __restrict__ bfc, float* __restrict__ out, int n) {
    __shared__ float sb[16];
    __shared__ float sw[16];
    __shared__ float sbf;
    if (threadIdx.x < 16) {
        sb[threadIdx.x] = b2[threadIdx.x];
        sw[threadIdx.x] = Wfc[threadIdx.x];
    }
    if (threadIdx.x == 0) sbf = bfc[0];
    __syncthreads();
    int i = blockIdx.x * blockDim.x + threadIdx.x;
    if (i >= n) return;

    float di = g_dinv[i];
    const float* g2r = g_g2 + (size_t)i * 16;
    const float* a2r = g_acc2 + (size_t)i * 16;

    float z = sbf;
#pragma unroll
    for (int f4 = 0; f4 < 4; f4++) {
        float4 a = reinterpret_cast<const float4*>(a2r)[f4];
        float4 g = reinterpret_cast<const float4*>(g2r)[f4];
        const float* ap = &a.x;
        const float* gp = &g.x;
#pragma unroll
        for (int c = 0; c < 4; c++) {
            int f = f4 * 4 + c;
            float h = fmaxf(di * (ap[c] + gp[c]) + sb[f], 0.f);
            z = fmaf(h, sw[f], z);
        }
    }
    out[i] = 1.0f / (1.0f + expf(-z));
}

extern "C" void kernel_launch(void* const* d_in, const int* in_sizes, int n_in,
                              void* d_out, int out_size) {
    const float* x   = (const float*)d_in[0];
    const int*   ei  = (const int*)d_in[1];
    const float* W1  = (const float*)d_in[2];
    const float* b1  = (const float*)d_in[3];
    const float* W2  = (const float*)d_in[4];
    const float* b2  = (const float*)d_in[5];
    const float* Wfc = (const float*)d_in[6];
    const float* bfc = (const float*)d_in[7];
    float* out = (float*)d_out;

    int n = in_sizes[0] / 8;   // nodes
    int e = in_sizes[1] / 2;   // edges
    const int* src = ei;
    const int* dst = ei + e;

    const int B = 256;
    int gn = (n + B - 1) / B;
    int ge = (e + B - 1) / B;

    k_deg_init<<<gn, B>>>(n);
    k_deg_count<<<ge, B>>>(dst, e);
    k_prep1<<<gn, B>>>(x, W1, n);
    k_scatter<8, true><<<ge, B>>>(src, dst, e);
    k_mid<<<gn, B>>>(W2, b1, n);
    k_scatter<4, false><<<ge, B>>>(src, dst, e);
    k_final<<<gn, B>>>(b2, Wfc, bfc, out, n);
}

// round 2
// speedup vs baseline: 1.7276x; 1.7276x over previous
#include <cuda_runtime.h>
#include <math.h>

// Problem-fixed maxima (registry problem: N=100000, E=1600000)
#define N_MAX 100000
#define E_MAX 1600000

// Scratch (allocation-free rule: __device__ globals)
__device__ float g_deg[N_MAX];
__device__ float g_dinv[N_MAX];
__device__ __align__(16) float g_g1[N_MAX * 32];
__device__ __align__(16) float g_acc1[N_MAX * 32];
__device__ __align__(16) float g_g2[N_MAX * 16];
__device__ __align__(16) float g_acc2[N_MAX * 16];

// K1: deg[i] = 1 (self-loop)
__global__ void k_deg_init(int n) {
    int i = blockIdx.x * blockDim.x + threadIdx.x;
    if (i < n) g_deg[i] = 1.0f;
}

// K2: deg[dst] += 1 per edge (RED, no return)
__global__ void k_deg_count(const int* __restrict__ dst, int e) {
    int j = blockIdx.x * blockDim.x + threadIdx.x;
    if (j < e) atomicAdd(&g_deg[dst[j]], 1.0f);
}

// K3: dinv = rsqrt(deg); g1 = (x @ W1) * dinv; acc1 = 0
__global__ void k_prep1(const float* __restrict__ x, const float* __restrict__ W1, int n) {
    __shared__ float sW[8 * 32];
    for (int t = threadIdx.x; t < 256; t += blockDim.x) sW[t] = W1[t];
    __syncthreads();
    int i = blockIdx.x * blockDim.x + threadIdx.x;
    if (i >= n) return;

    float4 xa = *reinterpret_cast<const float4*>(x + (size_t)i * 8);
    float4 xb = *reinterpret_cast<const float4*>(x + (size_t)i * 8 + 4);
    float xv[8] = {xa.x, xa.y, xa.z, xa.w, xb.x, xb.y, xb.z, xb.w};

    float di = rsqrtf(g_deg[i]);
    g_dinv[i] = di;

    float* g1r = g_g1 + (size_t)i * 32;
    float* a1r = g_acc1 + (size_t)i * 32;
#pragma unroll
    for (int f4 = 0; f4 < 8; f4++) {
        float4 hv;
        float* hp = &hv.x;
#pragma unroll
        for (int c = 0; c < 4; c++) {
            int f = f4 * 4 + c;
            float h = 0.f;
#pragma unroll
            for (int k = 0; k < 8; k++) h = fmaf(xv[k], sW[k * 32 + f], h);
            hp[c] = h * di;
        }
        reinterpret_cast<float4*>(g1r)[f4] = hv;
        reinterpret_cast<float4*>(a1r)[f4] = make_float4(0.f, 0.f, 0.f, 0.f);
    }
}

// K4/K6: acc[dst] += g[src], coalesced: F4 threads cooperate on one edge.
// Lane c = tid % F4 handles float4 chunk c, so F4 consecutive lanes touch
// one contiguous 128B (F4=8) row -> 1 L1 wavefront per edge-load instead of 8.
template <int F4, bool LAYER1>
__global__ void k_scatter_vec(const int* __restrict__ src, const int* __restrict__ dst, int e) {
    int t = blockIdx.x * blockDim.x + threadIdx.x;
    int j = t >> (F4 == 8 ? 3 : 2);
    int c = t & (F4 - 1);
    if (j >= e) return;
    int s = __ldg(src + j);
    int d = __ldg(dst + j);
    const float4* gs = reinterpret_cast<const float4*>((LAYER1 ? g_g1 : g_g2) + (size_t)s * F4 * 4);
    float4* ad = reinterpret_cast<float4*>((LAYER1 ? g_acc1 : g_acc2) + (size_t)d * F4 * 4);
    float4 v = __ldg(gs + c);
    asm volatile("red.global.add.v4.f32 [%0], {%1, %2, %3, %4};"
                 :: "l"(ad + c), "f"(v.x), "f"(v.y), "f"(v.z), "f"(v.w)
                 : "memory");
}

// K5: h1 = relu(dinv*(acc1+g1) + b1); g2 = (h1 @ W2) * dinv; acc2 = 0
__global__ void k_mid(const float* __restrict__ W2, const float* __restrict__ b1, int n) {
    __shared__ float sW[32 * 16];
    __shared__ float sb[32];
    for (int t = threadIdx.x; t < 512; t += blockDim.x) sW[t] = W2[t];
    if (threadIdx.x < 32) sb[threadIdx.x] = b1[threadIdx.x];
    __syncthreads();
    int i = blockIdx.x * blockDim.x + threadIdx.x;
    if (i >= n) return;

    float di = g_dinv[i];
    const float* g1r = g_g1 + (size_t)i * 32;
    const float* a1r = g_acc1 + (size_t)i * 32;

    float h1[32];
#pragma unroll
    for (int f4 = 0; f4 < 8; f4++) {
        float4 a = reinterpret_cast<const float4*>(a1r)[f4];
        float4 g = reinterpret_cast<const float4*>(g1r)[f4];
        h1[f4 * 4 + 0] = fmaxf(di * (a.x + g.x) + sb[f4 * 4 + 0], 0.f);
        h1[f4 * 4 + 1] = fmaxf(di * (a.y + g.y) + sb[f4 * 4 + 1], 0.f);
        h1[f4 * 4 + 2] = fmaxf(di * (a.z + g.z) + sb[f4 * 4 + 2], 0.f);
        h1[f4 * 4 + 3] = fmaxf(di * (a.w + g.w) + sb[f4 * 4 + 3], 0.f);
    }

    float* g2r = g_g2 + (size_t)i * 16;
    float* a2r = g_acc2 + (size_t)i * 16;
#pragma unroll
    for (int f4 = 0; f4 < 4; f4++) {
        float4 hv;
        float* hp = &hv.x;
#pragma unroll
        for (int c = 0; c < 4; c++) {
            int f = f4 * 4 + c;
            float h = 0.f;
#pragma unroll
            for (int k = 0; k < 32; k++) h = fmaf(h1[k], sW[k * 16 + f], h);
            hp[c] = h * di;
        }
        reinterpret_cast<float4*>(g2r)[f4] = hv;
        reinterpret_cast<float4*>(a2r)[f4] = make_float4(0.f, 0.f, 0.f, 0.f);
    }
}

// K7: h2 = relu(dinv*(acc2+g2) + b2); out = sigmoid(h2 @ Wfc + bfc)
__global__ void k_final(const float* __restrict__ b2, const float* __restrict__ Wfc,
                        const float* __restrict__ bfc, float* __restrict__ out, int n) {
    __shared__ float sb[16];
    __shared__ float sw[16];
    __shared__ float sbf;
    if (threadIdx.x < 16) {
        sb[threadIdx.x] = b2[threadIdx.x];
        sw[threadIdx.x] = Wfc[threadIdx.x];
    }
    if (threadIdx.x == 0) sbf = bfc[0];
    __syncthreads();
    int i = blockIdx.x * blockDim.x + threadIdx.x;
    if (i >= n) return;

    float di = g_dinv[i];
    const float* g2r = g_g2 + (size_t)i * 16;
    const float* a2r = g_acc2 + (size_t)i * 16;

    float z = sbf;
#pragma unroll
    for (int f4 = 0; f4 < 4; f4++) {
        float4 a = reinterpret_cast<const float4*>(a2r)[f4];
        float4 g = reinterpret_cast<const float4*>(g2r)[f4];
        const float* ap = &a.x;
        const float* gp = &g.x;
#pragma unroll
        for (int c = 0; c < 4; c++) {
            int f = f4 * 4 + c;
            float h = fmaxf(di * (ap[c] + gp[c]) + sb[f], 0.f);
            z = fmaf(h, sw[f], z);
        }
    }
    out[i] = 1.0f / (1.0f + expf(-z));
}

extern "C" void kernel_launch(void* const* d_in, const int* in_sizes, int n_in,
                              void* d_out, int out_size) {
    const float* x   = (const float*)d_in[0];
    const int*   ei  = (const int*)d_in[1];
    const float* W1  = (const float*)d_in[2];
    const float* b1  = (const float*)d_in[3];
    const float* W2  = (const float*)d_in[4];
    const float* b2  = (const float*)d_in[5];
    const float* Wfc = (const float*)d_in[6];
    const float* bfc = (const float*)d_in[7];
    float* out = (float*)d_out;

    int n = in_sizes[0] / 8;   // nodes
    int e = in_sizes[1] / 2;   // edges
    const int* src = ei;
    const int* dst = ei + e;

    const int B = 256;
    int gn = (n + B - 1) / B;
    int ge = (e + B - 1) / B;
    int ge8 = ((e * 8) + B - 1) / B;  // 8 threads per edge (layer 1)
    int ge4 = ((e * 4) + B - 1) / B;  // 4 threads per edge (layer 2)

    k_deg_init<<<gn, B>>>(n);
    k_deg_count<<<ge, B>>>(dst, e);
    k_prep1<<<gn, B>>>(x, W1, n);
    k_scatter_vec<8, true><<<ge8, B>>>(src, dst, e);
    k_mid<<<gn, B>>>(W2, b1, n);
    k_scatter_vec<4, false><<<ge4, B>>>(src, dst, e);
    k_final<<<gn, B>>>(b2, Wfc, bfc, out, n);
}

// round 4
// speedup vs baseline: 1.9643x; 1.1370x over previous
#include <cuda_runtime.h>
#include <math.h>

// Problem-fixed maxima (registry problem: N=100000, E=1600000)
#define N_MAX 100000
#define E_MAX 1600000
#define NB 256

// Scratch (allocation-free rule: __device__ globals)
__device__ int   g_degi[N_MAX];
__device__ int   g_rowptr[N_MAX + 1];
__device__ int   g_cursor[N_MAX];
__device__ int   g_col[E_MAX];
__device__ int   g_bsum[512];
__device__ int   g_boff[512];
__device__ float g_dinv[N_MAX];
__device__ __align__(16) float g_g1[N_MAX * 32];
__device__ __align__(16) float g_h1[N_MAX * 32];
__device__ __align__(16) float g_g2[N_MAX * 16];

// ---------- CSR build ----------

__global__ void k_deg_zero(int n) {
    int i = blockIdx.x * blockDim.x + threadIdx.x;
    if (i < n) g_degi[i] = 0;
}

__global__ void k_deg_count(const int* __restrict__ dst, int e) {
    int j = blockIdx.x * blockDim.x + threadIdx.x;
    if (j < e) atomicAdd(&g_degi[dst[j]], 1);
}

// per-block sums of deg
__global__ void k_scan1(int n) {
    __shared__ int s[NB];
    int i = blockIdx.x * NB + threadIdx.x;
    s[threadIdx.x] = (i < n) ? g_degi[i] : 0;
    __syncthreads();
    for (int off = NB / 2; off > 0; off >>= 1) {
        if (threadIdx.x < off) s[threadIdx.x] += s[threadIdx.x + off];
        __syncthreads();
    }
    if (threadIdx.x == 0) g_bsum[blockIdx.x] = s[0];
}

// 1 block: exclusive scan of block sums (nblk <= 512)
__global__ void k_scan2(int nblk, int n, int e) {
    __shared__ int s[512];
    int t = threadIdx.x;
    int orig = (t < nblk) ? g_bsum[t] : 0;
    s[t] = orig;
    __syncthreads();
    for (int off = 1; off < 512; off <<= 1) {
        int v = (t >= off) ? s[t - off] : 0;
        __syncthreads();
        s[t] += v;
        __syncthreads();
    }
    if (t < nblk) g_boff[t] = s[t] - orig;  // exclusive
    if (t == 0) g_rowptr[n] = e;
}

// per-element exclusive scan + cursor + dinv
__global__ void k_scan3(int n) {
    __shared__ int s[NB];
    int t = threadIdx.x;
    int i = blockIdx.x * NB + t;
    int d = (i < n) ? g_degi[i] : 0;
    s[t] = d;
    __syncthreads();
    for (int off = 1; off < NB; off <<= 1) {
        int v = (t >= off) ? s[t - off] : 0;
        __syncthreads();
        s[t] += v;
        __syncthreads();
    }
    if (i < n) {
        int excl = s[t] - d + g_boff[blockIdx.x];
        g_rowptr[i] = excl;
        g_cursor[i] = excl;
        g_dinv[i] = rsqrtf((float)(d + 1));
    }
}

__global__ void k_fill(const int* __restrict__ src, const int* __restrict__ dst, int e) {
    int j = blockIdx.x * blockDim.x + threadIdx.x;
    if (j >= e) return;
    int p = atomicAdd(&g_cursor[dst[j]], 1);
    g_col[p] = src[j];
}

// ---------- layer compute ----------

// g1 = (x @ W1) * dinv
__global__ void k_prep1(const float* __restrict__ x, const float* __restrict__ W1, int n) {
    __shared__ float sW[8 * 32];
    for (int t = threadIdx.x; t < 256; t += blockDim.x) sW[t] = W1[t];
    __syncthreads();
    int i = blockIdx.x * blockDim.x + threadIdx.x;
    if (i >= n) return;

    float4 xa = *reinterpret_cast<const float4*>(x + (size_t)i * 8);
    float4 xb = *reinterpret_cast<const float4*>(x + (size_t)i * 8 + 4);
    float xv[8] = {xa.x, xa.y, xa.z, xa.w, xb.x, xb.y, xb.z, xb.w};
    float di = g_dinv[i];

    float* g1r = g_g1 + (size_t)i * 32;
#pragma unroll
    for (int f4 = 0; f4 < 8; f4++) {
        float4 hv;
        float* hp = &hv.x;
#pragma unroll
        for (int c = 0; c < 4; c++) {
            int f = f4 * 4 + c;
            float h = 0.f;
#pragma unroll
            for (int k = 0; k < 8; k++) h = fmaf(xv[k], sW[k * 32 + f], h);
            hp[c] = h * di;
        }
        reinterpret_cast<float4*>(g1r)[f4] = hv;
    }
}

__device__ __forceinline__ void f4add(float4& a, const float4& b) {
    a.x += b.x; a.y += b.y; a.z += b.z; a.w += b.w;
}

// Gather layer 1 (32 feats, 8 lanes/node): h1 = relu(dinv*(self + sum g1[col]) + b1)
__global__ void k_gather1(const float* __restrict__ b1, int n) {
    int t = blockIdx.x * blockDim.x + threadIdx.x;
    int g = t >> 3, c = t & 7;
    if (g >= n) return;
    int beg = __ldg(&g_rowptr[g]);
    int end = __ldg(&g_rowptr[g + 1]);
    const float4* G = reinterpret_cast<const float4*>(g_g1);

    float4 acc = __ldg(G + (size_t)g * 8 + c);  // self-loop term
    int p = beg;
    for (; p + 4 <= end; p += 4) {
        int s0 = __ldg(g_col + p);
        int s1 = __ldg(g_col + p + 1);
        int s2 = __ldg(g_col + p + 2);
        int s3 = __ldg(g_col + p + 3);
        float4 v0 = __ldg(G + (size_t)s0 * 8 + c);
        float4 v1 = __ldg(G + (size_t)s1 * 8 + c);
        float4 v2 = __ldg(G + (size_t)s2 * 8 + c);
        float4 v3 = __ldg(G + (size_t)s3 * 8 + c);
        f4add(v0, v1); f4add(v2, v3); f4add(acc, v0); f4add(acc, v2);
    }
    for (; p < end; p++) {
        int s = __ldg(g_col + p);
        float4 v = __ldg(G + (size_t)s * 8 + c);
        f4add(acc, v);
    }

    float di = __ldg(&g_dinv[g]);
    float4 bb = __ldg(reinterpret_cast<const float4*>(b1) + c);
    float4 h;
    h.x = fmaxf(fmaf(di, acc.x, bb.x), 0.f);
    h.y = fmaxf(fmaf(di, acc.y, bb.y), 0.f);
    h.z = fmaxf(fmaf(di, acc.z, bb.z), 0.f);
    h.w = fmaxf(fmaf(di, acc.w, bb.w), 0.f);
    reinterpret_cast<float4*>(g_h1)[(size_t)g * 8 + c] = h;
}

// g2 = (h1 @ W2) * dinv
__global__ void k_mid(const float* __restrict__ W2, int n) {
    __shared__ float sW[32 * 16];
    for (int t = threadIdx.x; t < 512; t += blockDim.x) sW[t] = W2[t];
    __syncthreads();
    int i = blockIdx.x * blockDim.x + threadIdx.x;
    if (i >= n) return;

    float di = g_dinv[i];
    const float* h1r = g_h1 + (size_t)i * 32;
    float h1[32];
#pragma unroll
    for (int f4 = 0; f4 < 8; f4++) {
        float4 v = reinterpret_cast<const float4*>(h1r)[f4];
        h1[f4 * 4 + 0] = v.x; h1[f4 * 4 + 1] = v.y;
        h1[f4 * 4 + 2] = v.z; h1[f4 * 4 + 3] = v.w;
    }

    float* g2r = g_g2 + (size_t)i * 16;
#pragma unroll
    for (int f4 = 0; f4 < 4; f4++) {
        float4 hv;
        float* hp = &hv.x;
#pragma unroll
        for (int c = 0; c < 4; c++) {
            int f = f4 * 4 + c;
            float h = 0.f;
#pragma unroll
            for (int k = 0; k < 32; k++) h = fmaf(h1[k], sW[k * 16 + f], h);
            hp[c] = h * di;
        }
        reinterpret_cast<float4*>(g2r)[f4] = hv;
    }
}

// Gather layer 2 fused with FC head (16 feats, 4 lanes/node):
// h2 = relu(dinv*(self + sum g2[col]) + b2); out = sigmoid(h2.Wfc + bfc)
__global__ void k_gather2_final(const float* __restrict__ b2, const float* __restrict__ Wfc,
                                const float* __restrict__ bfc, float* __restrict__ out, int n) {
    int t = blockIdx.x * blockDim.x + threadIdx.x;
    int g = t >> 2, c = t & 3;
    if (g >= n) return;
    int beg = __ldg(&g_rowptr[g]);
    int end = __ldg(&g_rowptr[g + 1]);
    const float4* G = reinterpret_cast<const float4*>(g_g2);

    float4 acc = __ldg(G + (size_t)g * 4 + c);  // self-loop term
    int p = beg;
    for (; p + 4 <= end; p += 4) {
        int s0 = __ldg(g_col + p);
        int s1 = __ldg(g_col + p + 1);
        int s2 = __ldg(g_col + p + 2);
        int s3 = __ldg(g_col + p + 3);
        float4 v0 = __ldg(G + (size_t)s0 * 4 + c);
        float4 v1 = __ldg(G + (size_t)s1 * 4 + c);
        float4 v2 = __ldg(G + (size_t)s2 * 4 + c);
        float4 v3 = __ldg(G + (size_t)s3 * 4 + c);
        f4add(v0, v1); f4add(v2, v3); f4add(acc, v0); f4add(acc, v2);
    }
    for (; p < end; p++) {
        int s = __ldg(g_col + p);
        float4 v = __ldg(G + (size_t)s * 4 + c);
        f4add(acc, v);
    }

    float di = __ldg(&g_dinv[g]);
    float4 bb = __ldg(reinterpret_cast<const float4*>(b2) + c);
    float4 ww = __ldg(reinterpret_cast<const float4*>(Wfc) + c);
    float h0 = fmaxf(fmaf(di, acc.x, bb.x), 0.f);
    float h1 = fmaxf(fmaf(di, acc.y, bb.y), 0.f);
    float h2 = fmaxf(fmaf(di, acc.z, bb.z), 0.f);
    float h3 = fmaxf(fmaf(di, acc.w, bb.w), 0.f);
    float z = h0 * ww.x + h1 * ww.y + h2 * ww.z + h3 * ww.w;
    z += __shfl_xor_sync(0xffffffffu, z, 1);
    z += __shfl_xor_sync(0xffffffffu, z, 2);
    if (c == 0) out[g] = 1.0f / (1.0f + expf(-(z + __ldg(bfc))));
}

extern "C" void kernel_launch(void* const* d_in, const int* in_sizes, int n_in,
                              void* d_out, int out_size) {
    const float* x   = (const float*)d_in[0];
    const int*   ei  = (const int*)d_in[1];
    const float* W1  = (const float*)d_in[2];
    const float* b1  = (const float*)d_in[3];
    const float* W2  = (const float*)d_in[4];
    const float* b2  = (const float*)d_in[5];
    const float* Wfc = (const float*)d_in[6];
    const float* bfc = (const float*)d_in[7];
    float* out = (float*)d_out;

    int n = in_sizes[0] / 8;   // nodes
    int e = in_sizes[1] / 2;   // edges
    const int* src = ei;
    const int* dst = ei + e;

    int gn = (n + NB - 1) / NB;            // node blocks (= nblk for scans)
    int ge = (e + NB - 1) / NB;            // edge blocks
    int g8 = ((n * 8) + NB - 1) / NB;      // 8 lanes/node
    int g4 = ((n * 4) + NB - 1) / NB;      // 4 lanes/node

    k_deg_zero<<<gn, NB>>>(n);
    k_deg_count<<<ge, NB>>>(dst, e);
    k_scan1<<<gn, NB>>>(n);
    k_scan2<<<1, 512>>>(gn, n, e);
    k_scan3<<<gn, NB>>>(n);
    k_fill<<<ge, NB>>>(src, dst, e);
    k_prep1<<<gn, NB>>>(x, W1, n);
    k_gather1<<<g8, NB>>>(b1, n);
    k_mid<<<gn, NB>>>(W2, n);
    k_gather2_final<<<g4, NB>>>(b2, Wfc, bfc, out, n);
}

// round 6
// speedup vs baseline: 2.3832x; 1.2132x over previous
#include <cuda_runtime.h>
#include <math.h>

// Problem-fixed maxima (registry problem: N=100000, E=1600000)
#define N_MAX 100000
#define E_MAX 1600000
#define NB 256

// Scratch (allocation-free rule: __device__ globals)
__device__ int   g_degi[N_MAX];
__device__ int   g_rowptr[N_MAX + 1];
__device__ int   g_slot[E_MAX];
__device__ int   g_col[E_MAX];
__device__ int   g_bsum[512];
__device__ float g_dinv[N_MAX];
__device__ __align__(16) float g_xs[N_MAX * 8];   // x * dinv (pre-scaled inputs)
__device__ __align__(16) float g_h1[N_MAX * 32];  // layer-1 activations
__device__ __align__(16) float g_g2[N_MAX * 16];  // (h1 @ W2) * dinv

// ---------- CSR build ----------

__global__ void k_deg_zero(int n) {
    int i = blockIdx.x * blockDim.x + threadIdx.x;
    if (i < n) g_degi[i] = 0;
}

// deg count + per-edge slot in one atomic pass
__global__ void k_deg_slot(const int* __restrict__ dst, int e) {
    int j = blockIdx.x * blockDim.x + threadIdx.x;
    if (j < e) g_slot[j] = atomicAdd(&g_degi[dst[j]], 1);
}

// per-block sums of deg
__global__ void k_scan1(int n) {
    __shared__ int s[NB];
    int i = blockIdx.x * NB + threadIdx.x;
    s[threadIdx.x] = (i < n) ? g_degi[i] : 0;
    __syncthreads();
    for (int off = NB / 2; off > 0; off >>= 1) {
        if (threadIdx.x < off) s[threadIdx.x] += s[threadIdx.x + off];
        __syncthreads();
    }
    if (threadIdx.x == 0) g_bsum[blockIdx.x] = s[0];
}

// Fused: per-block bsum-prefix (replaces global scan kernel) + per-element
// exclusive scan -> rowptr; also dinv and xs = x * dinv.
__global__ void k_scan3b(const float* __restrict__ x, int n) {
    __shared__ int rbuf[NB];
    __shared__ int s[NB];
    int bid = blockIdx.x, t = threadIdx.x;

    // block offset = sum of bsum[0..bid)
    int partial = 0;
    for (int j = t; j < bid; j += NB) partial += g_bsum[j];
    rbuf[t] = partial;
    __syncthreads();
    for (int off = NB / 2; off > 0; off >>= 1) {
        if (t < off) rbuf[t] += rbuf[t + off];
        __syncthreads();
    }
    int blockoff = rbuf[0];

    int i = bid * NB + t;
    int d = (i < n) ? g_degi[i] : 0;
    s[t] = d;
    __syncthreads();
    for (int off = 1; off < NB; off <<= 1) {
        int v = (t >= off) ? s[t - off] : 0;
        __syncthreads();
        s[t] += v;
        __syncthreads();
    }
    if (i < n) {
        int excl = s[t] - d + blockoff;
        g_rowptr[i] = excl;
        if (i == n - 1) g_rowptr[n] = excl + d;
        float di = rsqrtf((float)(d + 1));
        g_dinv[i] = di;
        float4 xa = __ldg(reinterpret_cast<const float4*>(x + (size_t)i * 8));
        float4 xb = __ldg(reinterpret_cast<const float4*>(x + (size_t)i * 8) + 1);
        xa.x *= di; xa.y *= di; xa.z *= di; xa.w *= di;
        xb.x *= di; xb.y *= di; xb.z *= di; xb.w *= di;
        reinterpret_cast<float4*>(g_xs)[(size_t)i * 2]     = xa;
        reinterpret_cast<float4*>(g_xs)[(size_t)i * 2 + 1] = xb;
    }
}

// atomic-free bucket fill using precomputed slots
__global__ void k_fill2(const int* __restrict__ src, const int* __restrict__ dst, int e) {
    int j = blockIdx.x * blockDim.x + threadIdx.x;
    if (j >= e) return;
    int d = __ldg(dst + j);
    int p = __ldg(&g_rowptr[d]) + g_slot[j];
    g_col[p] = __ldg(src + j);
}

// ---------- layer compute ----------

__device__ __forceinline__ void f4add(float4& a, const float4& b) {
    a.x += b.x; a.y += b.y; a.z += b.z; a.w += b.w;
}

// Layer 1, linearity-exploiting: gather 8-dim xs (32B/row), THEN apply W1.
// 2 lanes per node, lane c holds dims [4c, 4c+4); after the edge loop the
// lanes exchange their float4 via shfl so each lane has the full 8-dim agg,
// then each computes 16 of the 32 outputs. h1 = relu(dinv*agg @ W1 + b1).
__global__ void k_gather1w(const float* __restrict__ W1, const float* __restrict__ b1, int n) {
    __shared__ float sW[8 * 32];
    __shared__ float sb[32];
    for (int t = threadIdx.x; t < 256; t += blockDim.x) sW[t] = W1[t];
    if (threadIdx.x < 32) sb[threadIdx.x] = b1[threadIdx.x];
    __syncthreads();

    int t = blockIdx.x * blockDim.x + threadIdx.x;
    int g = t >> 1, c = t & 1;
    if (g >= n) return;  // n*2 = 200000: exits are whole warps, shfl below safe
    int beg = __ldg(&g_rowptr[g]);
    int end = __ldg(&g_rowptr[g + 1]);
    const float4* X = reinterpret_cast<const float4*>(g_xs);

    float4 acc = __ldg(X + (size_t)g * 2 + c);  // self-loop term (pre-scaled)
    int p = beg;
    for (; p + 4 <= end; p += 4) {
        int s0 = __ldg(g_col + p);
        int s1 = __ldg(g_col + p + 1);
        int s2 = __ldg(g_col + p + 2);
        int s3 = __ldg(g_col + p + 3);
        float4 v0 = __ldg(X + (size_t)s0 * 2 + c);
        float4 v1 = __ldg(X + (size_t)s1 * 2 + c);
        float4 v2 = __ldg(X + (size_t)s2 * 2 + c);
        float4 v3 = __ldg(X + (size_t)s3 * 2 + c);
        f4add(v0, v1); f4add(v2, v3); f4add(acc, v0); f4add(acc, v2);
    }
    for (; p < end; p++) {
        int s = __ldg(g_col + p);
        float4 v = __ldg(X + (size_t)s * 2 + c);
        f4add(acc, v);
    }

    float di = __ldg(&g_dinv[g]);
    acc.x *= di; acc.y *= di; acc.z *= di; acc.w *= di;

    // exchange halves: partner lane = t ^ 1 (same node)
    float ox = __shfl_xor_sync(0xffffffffu, acc.x, 1);
    float oy = __shfl_xor_sync(0xffffffffu, acc.y, 1);
    float oz = __shfl_xor_sync(0xffffffffu, acc.z, 1);
    float ow = __shfl_xor_sync(0xffffffffu, acc.w, 1);
    // full 8-dim vector: dims 0-3 from lane0's acc, dims 4-7 from lane1's acc
    float a0 = c ? ox : acc.x, a1 = c ? oy : acc.y, a2 = c ? oz : acc.z, a3 = c ? ow : acc.w;
    float a4 = c ? acc.x : ox, a5 = c ? acc.y : oy, a6 = c ? acc.z : oz, a7 = c ? acc.w : ow;

    int base = c * 16;  // this lane's output range
    float out[16];
#pragma unroll
    for (int k = 0; k < 16; k++) {
        int f = base + k;
        float h = a0 * sW[f] + a1 * sW[32 + f] + a2 * sW[64 + f] + a3 * sW[96 + f]
                + a4 * sW[128 + f] + a5 * sW[160 + f] + a6 * sW[192 + f] + a7 * sW[224 + f];
        out[k] = fmaxf(h + sb[f], 0.f);
    }
    float4* H = reinterpret_cast<float4*>(g_h1 + (size_t)g * 32 + base);
    H[0] = make_float4(out[0], out[1], out[2], out[3]);
    H[1] = make_float4(out[4], out[5], out[6], out[7]);
    H[2] = make_float4(out[8], out[9], out[10], out[11]);
    H[3] = make_float4(out[12], out[13], out[14], out[15]);
}

// g2 = (h1 @ W2) * dinv  (project to the SMALLER dim before gathering)
__global__ void k_mid(const float* __restrict__ W2, int n) {
    __shared__ float sW[32 * 16];
    for (int t = threadIdx.x; t < 512; t += blockDim.x) sW[t] = W2[t];
    __syncthreads();
    int i = blockIdx.x * blockDim.x + threadIdx.x;
    if (i >= n) return;

    float di = g_dinv[i];
    const float* h1r = g_h1 + (size_t)i * 32;
    float h1[32];
#pragma unroll
    for (int f4 = 0; f4 < 8; f4++) {
        float4 v = reinterpret_cast<const float4*>(h1r)[f4];
        h1[f4 * 4 + 0] = v.x; h1[f4 * 4 + 1] = v.y;
        h1[f4 * 4 + 2] = v.z; h1[f4 * 4 + 3] = v.w;
    }

    float* g2r = g_g2 + (size_t)i * 16;
#pragma unroll
    for (int f4 = 0; f4 < 4; f4++) {
        float4 hv;
        float* hp = &hv.x;
#pragma unroll
        for (int cc = 0; cc < 4; cc++) {
            int f = f4 * 4 + cc;
            float h = 0.f;
#pragma unroll
            for (int k = 0; k < 32; k++) h = fmaf(h1[k], sW[k * 16 + f], h);
            hp[cc] = h * di;
        }
        reinterpret_cast<float4*>(g2r)[f4] = hv;
    }
}

// Gather layer 2 fused with FC head (16 feats, 4 lanes/node):
// h2 = relu(dinv*(self + sum g2[col]) + b2); out = sigmoid(h2.Wfc + bfc)
__global__ void k_gather2_final(const float* __restrict__ b2, const float* __restrict__ Wfc,
                                const float* __restrict__ bfc, float* __restrict__ out, int n) {
    int t = blockIdx.x * blockDim.x + threadIdx.x;
    int g = t >> 2, c = t & 3;
    if (g >= n) return;  // n*4 = 400000: whole-warp exits, shfl safe
    int beg = __ldg(&g_rowptr[g]);
    int end = __ldg(&g_rowptr[g + 1]);
    const float4* G = reinterpret_cast<const float4*>(g_g2);

    float4 acc = __ldg(G + (size_t)g * 4 + c);  // self-loop term
    int p = beg;
    for (; p + 4 <= end; p += 4) {
        int s0 = __ldg(g_col + p);
        int s1 = __ldg(g_col + p + 1);
        int s2 = __ldg(g_col + p + 2);
        int s3 = __ldg(g_col + p + 3);
        float4 v0 = __ldg(G + (size_t)s0 * 4 + c);
        float4 v1 = __ldg(G + (size_t)s1 * 4 + c);
        float4 v2 = __ldg(G + (size_t)s2 * 4 + c);
        float4 v3 = __ldg(G + (size_t)s3 * 4 + c);
        f4add(v0, v1); f4add(v2, v3); f4add(acc, v0); f4add(acc, v2);
    }
    for (; p < end; p++) {
        int s = __ldg(g_col + p);
        float4 v = __ldg(G + (size_t)s * 4 + c);
        f4add(acc, v);
    }

    float di = __ldg(&g_dinv[g]);
    float4 bb = __ldg(reinterpret_cast<const float4*>(b2) + c);
    float4 ww = __ldg(reinterpret_cast<const float4*>(Wfc) + c);
    float h0 = fmaxf(fmaf(di, acc.x, bb.x), 0.f);
    float h1 = fmaxf(fmaf(di, acc.y, bb.y), 0.f);
    float h2 = fmaxf(fmaf(di, acc.z, bb.z), 0.f);
    float h3 = fmaxf(fmaf(di, acc.w, bb.w), 0.f);
    float z = h0 * ww.x + h1 * ww.y + h2 * ww.z + h3 * ww.w;
    z += __shfl_xor_sync(0xffffffffu, z, 1);
    z += __shfl_xor_sync(0xffffffffu, z, 2);
    if (c == 0) out[g] = 1.0f / (1.0f + expf(-(z + __ldg(bfc))));
}

extern "C" void kernel_launch(void* const* d_in, const int* in_sizes, int n_in,
                              void* d_out, int out_size) {
    const float* x   = (const float*)d_in[0];
    const int*   ei  = (const int*)d_in[1];
    const float* W1  = (const float*)d_in[2];
    const float* b1  = (const float*)d_in[3];
    const float* W2  = (const float*)d_in[4];
    const float* b2  = (const float*)d_in[5];
    const float* Wfc = (const float*)d_in[6];
    const float* bfc = (const float*)d_in[7];
    float* out = (float*)d_out;

    int n = in_sizes[0] / 8;   // nodes
    int e = in_sizes[1] / 2;   // edges
    const int* src = ei;
    const int* dst = ei + e;

    int gn = (n + NB - 1) / NB;
    int ge = (e + NB - 1) / NB;
    int g2n = ((n * 2) + NB - 1) / NB;   // 2 lanes/node (layer-1 gather)
    int g4n = ((n * 4) + NB - 1) / NB;   // 4 lanes/node (layer-2 gather)

    k_deg_zero<<<gn, NB>>>(n);
    k_deg_slot<<<ge, NB>>>(dst, e);
    k_scan1<<<gn, NB>>>(n);
    k_scan3b<<<gn, NB>>>(x, n);
    k_fill2<<<ge, NB>>>(src, dst, e);
    k_gather1w<<<g2n, NB>>>(W1, b1, n);
    k_mid<<<gn, NB>>>(W2, n);
    k_gather2_final<<<g4n, NB>>>(b2, Wfc, bfc, out, n);
}

// round 7
// speedup vs baseline: 2.5244x; 1.0593x over previous
#include <cuda_runtime.h>
#include <math.h>

// Problem-fixed maxima (registry problem: N=100000, E=1600000)
#define N_MAX 100000
#define E_MAX 1600000
#define NB 256

// Scratch (allocation-free rule: __device__ globals)
__device__ int   g_degi[N_MAX];
__device__ int   g_rowptr[N_MAX + 1];
__device__ int   g_slot[E_MAX];
__device__ int   g_col[E_MAX];
__device__ int   g_bsum[512];
__device__ float g_dinv[N_MAX];
__device__ __align__(16) float g_xs[N_MAX * 8];   // x * dinv (pre-scaled inputs)
__device__ __align__(16) float g_g2[N_MAX * 16];  // (h1 @ W2) * dinv

// ---------- CSR build ----------

// deg count + per-edge slot in one atomic pass (g_degi zeroed by memset)
__global__ void k_deg_slot(const int* __restrict__ dst, int e) {
    int j = blockIdx.x * blockDim.x + threadIdx.x;
    if (j < e) g_slot[j] = atomicAdd(&g_degi[dst[j]], 1);
}

// per-block sums of deg (shfl reduction, 1 sync)
__global__ void k_scan1(int n) {
    int i = blockIdx.x * NB + threadIdx.x;
    int v = (i < n) ? g_degi[i] : 0;
#pragma unroll
    for (int off = 16; off > 0; off >>= 1) v += __shfl_xor_sync(0xffffffffu, v, off);
    __shared__ int ws[NB / 32];
    int wid = threadIdx.x >> 5, lane = threadIdx.x & 31;
    if (lane == 0) ws[wid] = v;
    __syncthreads();
    if (threadIdx.x == 0) {
        int s = 0;
#pragma unroll
        for (int w = 0; w < NB / 32; w++) s += ws[w];
        g_bsum[blockIdx.x] = s;
    }
}

// Fused: block offset from bsum + per-element exclusive scan -> rowptr;
// also dinv and xs = x * dinv. Shfl-based, 2 syncs.
__global__ void k_scan3b(const float* __restrict__ x, int n) {
    int bid = blockIdx.x, t = threadIdx.x;
    int wid = t >> 5, lane = t & 31;

    // partial of bsum[0..bid)
    int partial = 0;
    for (int j = t; j < bid; j += NB) partial += g_bsum[j];
#pragma unroll
    for (int off = 16; off > 0; off >>= 1) partial += __shfl_xor_sync(0xffffffffu, partial, off);

    __shared__ int pw[NB / 32];
    __shared__ int wsum[NB / 32];
    __shared__ int s_blockoff;
    if (lane == 0) pw[wid] = partial;

    // per-element: inclusive shfl scan within warp
    int i = bid * NB + t;
    int d = (i < n) ? g_degi[i] : 0;
    int sc = d;
#pragma unroll
    for (int off = 1; off < 32; off <<= 1) {
        int v = __shfl_up_sync(0xffffffffu, sc, off);
        if (lane >= off) sc += v;
    }
    if (lane == 31) wsum[wid] = sc;
    __syncthreads();

    if (t == 0) {
        int bo = 0;
#pragma unroll
        for (int w = 0; w < NB / 32; w++) bo += pw[w];
        s_blockoff = bo;
        // exclusive scan of the 8 warp sums
        int run = 0;
#pragma unroll
        for (int w = 0; w < NB / 32; w++) { int tmp = wsum[w]; wsum[w] = run; run += tmp; }
    }
    __syncthreads();

    if (i < n) {
        int excl = (sc - d) + wsum[wid] + s_blockoff;
        g_rowptr[i] = excl;
        if (i == n - 1) g_rowptr[n] = excl + d;
        float di = rsqrtf((float)(d + 1));
        g_dinv[i] = di;
        float4 xa = __ldg(reinterpret_cast<const float4*>(x + (size_t)i * 8));
        float4 xb = __ldg(reinterpret_cast<const float4*>(x + (size_t)i * 8) + 1);
        xa.x *= di; xa.y *= di; xa.z *= di; xa.w *= di;
        xb.x *= di; xb.y *= di; xb.z *= di; xb.w *= di;
        reinterpret_cast<float4*>(g_xs)[(size_t)i * 2]     = xa;
        reinterpret_cast<float4*>(g_xs)[(size_t)i * 2 + 1] = xb;
    }
}

// atomic-free bucket fill using precomputed slots
__global__ void k_fill2(const int* __restrict__ src, const int* __restrict__ dst, int e) {
    int j = blockIdx.x * blockDim.x + threadIdx.x;
    if (j >= e) return;
    int d = __ldg(dst + j);
    int p = __ldg(&g_rowptr[d]) + g_slot[j];
    g_col[p] = __ldg(src + j);
}

// ---------- layer compute ----------

__device__ __forceinline__ void f4add(float4& a, const float4& b) {
    a.x += b.x; a.y += b.y; a.z += b.z; a.w += b.w;
}

// Layer 1 + mid fused. 2 lanes/node; lane c gathers dims [4c,4c+4) of the
// 8-dim pre-scaled inputs, lanes exchange via shfl, each computes h1 for
// f in [16c,16c+16), then a 16x16 partial of h1@W2 + one shfl-xor exchange
// yields g2 = (h1 @ W2) * dinv. h1 never touches memory.
__global__ void k_gather1m(const float* __restrict__ W1, const float* __restrict__ b1,
                           const float* __restrict__ W2, int n) {
    __shared__ float sW1[8 * 32];
    __shared__ float sb1[32];
    __shared__ float sW2[32 * 16];
    for (int t = threadIdx.x; t < 256; t += blockDim.x) sW1[t] = W1[t];
    for (int t = threadIdx.x; t < 512; t += blockDim.x) sW2[t] = W2[t];
    if (threadIdx.x < 32) sb1[threadIdx.x] = b1[threadIdx.x];
    __syncthreads();

    int t = blockIdx.x * blockDim.x + threadIdx.x;
    int g = t >> 1, c = t & 1;
    if (g >= n) return;  // 2N = 200000 divisible by 32: whole-warp exits, shfl safe
    int beg = __ldg(&g_rowptr[g]);
    int end = __ldg(&g_rowptr[g + 1]);
    const float4* X = reinterpret_cast<const float4*>(g_xs);

    float4 acc = __ldg(X + (size_t)g * 2 + c);  // self-loop term (pre-scaled)
    int p = beg;
    for (; p + 4 <= end; p += 4) {
        int s0 = __ldg(g_col + p);
        int s1 = __ldg(g_col + p + 1);
        int s2 = __ldg(g_col + p + 2);
        int s3 = __ldg(g_col + p + 3);
        float4 v0 = __ldg(X + (size_t)s0 * 2 + c);
        float4 v1 = __ldg(X + (size_t)s1 * 2 + c);
        float4 v2 = __ldg(X + (size_t)s2 * 2 + c);
        float4 v3 = __ldg(X + (size_t)s3 * 2 + c);
        f4add(v0, v1); f4add(v2, v3); f4add(acc, v0); f4add(acc, v2);
    }
    for (; p < end; p++) {
        int s = __ldg(g_col + p);
        float4 v = __ldg(X + (size_t)s * 2 + c);
        f4add(acc, v);
    }

    float di = __ldg(&g_dinv[g]);
    acc.x *= di; acc.y *= di; acc.z *= di; acc.w *= di;

    // exchange halves: partner lane = t ^ 1 (same node)
    float ox = __shfl_xor_sync(0xffffffffu, acc.x, 1);
    float oy = __shfl_xor_sync(0xffffffffu, acc.y, 1);
    float oz = __shfl_xor_sync(0xffffffffu, acc.z, 1);
    float ow = __shfl_xor_sync(0xffffffffu, acc.w, 1);
    float a0 = c ? ox : acc.x, a1 = c ? oy : acc.y, a2 = c ? oz : acc.z, a3 = c ? ow : acc.w;
    float a4 = c ? acc.x : ox, a5 = c ? acc.y : oy, a6 = c ? acc.z : oz, a7 = c ? acc.w : ow;

    // h1 for this lane's 16 features
    int base = c * 16;
    float h1[16];
#pragma unroll
    for (int k = 0; k < 16; k++) {
        int f = base + k;
        float h = a0 * sW1[f] + a1 * sW1[32 + f] + a2 * sW1[64 + f] + a3 * sW1[96 + f]
                + a4 * sW1[128 + f] + a5 * sW1[160 + f] + a6 * sW1[192 + f] + a7 * sW1[224 + f];
        h1[k] = fmaxf(h + sb1[f], 0.f);
    }

    // partial of h1 @ W2 over this lane's 16 k-rows, all 16 outputs
    float z[16];
#pragma unroll
    for (int f = 0; f < 16; f++) {
        float s = 0.f;
#pragma unroll
        for (int k = 0; k < 16; k++) s = fmaf(h1[k], sW2[(base + k) * 16 + f], s);
        z[f] = s;
    }
    // complete with partner's partial, scale by dinv
#pragma unroll
    for (int f = 0; f < 16; f++)
        z[f] = (z[f] + __shfl_xor_sync(0xffffffffu, z[f], 1)) * di;

    // lane c writes outputs [8c, 8c+8)
    float4* G2 = reinterpret_cast<float4*>(g_g2 + (size_t)g * 16 + c * 8);
    int o = c * 8;
    G2[0] = make_float4(z[o + 0], z[o + 1], z[o + 2], z[o + 3]);
    G2[1] = make_float4(z[o + 4], z[o + 5], z[o + 6], z[o + 7]);
}

// Gather layer 2 fused with FC head (16 feats, 4 lanes/node):
// h2 = relu(dinv*(self + sum g2[col]) + b2); out = sigmoid(h2.Wfc + bfc)
__global__ void k_gather2_final(const float* __restrict__ b2, const float* __restrict__ Wfc,
                                const float* __restrict__ bfc, float* __restrict__ out, int n) {
    int t = blockIdx.x * blockDim.x + threadIdx.x;
    int g = t >> 2, c = t & 3;
    if (g >= n) return;  // 4N = 400000 divisible by 32: whole-warp exits, shfl safe
    int beg = __ldg(&g_rowptr[g]);
    int end = __ldg(&g_rowptr[g + 1]);
    const float4* G = reinterpret_cast<const float4*>(g_g2);

    float4 acc = __ldg(G + (size_t)g * 4 + c);  // self-loop term
    int p = beg;
    for (; p + 4 <= end; p += 4) {
        int s0 = __ldg(g_col + p);
        int s1 = __ldg(g_col + p + 1);
        int s2 = __ldg(g_col + p + 2);
        int s3 = __ldg(g_col + p + 3);
        float4 v0 = __ldg(G + (size_t)s0 * 4 + c);
        float4 v1 = __ldg(G + (size_t)s1 * 4 + c);
        float4 v2 = __ldg(G + (size_t)s2 * 4 + c);
        float4 v3 = __ldg(G + (size_t)s3 * 4 + c);
        f4add(v0, v1); f4add(v2, v3); f4add(acc, v0); f4add(acc, v2);
    }
    for (; p < end; p++) {
        int s = __ldg(g_col + p);
        float4 v = __ldg(G + (size_t)s * 4 + c);
        f4add(acc, v);
    }

    float di = __ldg(&g_dinv[g]);
    float4 bb = __ldg(reinterpret_cast<const float4*>(b2) + c);
    float4 ww = __ldg(reinterpret_cast<const float4*>(Wfc) + c);
    float h0 = fmaxf(fmaf(di, acc.x, bb.x), 0.f);
    float h1 = fmaxf(fmaf(di, acc.y, bb.y), 0.f);
    float h2 = fmaxf(fmaf(di, acc.z, bb.z), 0.f);
    float h3 = fmaxf(fmaf(di, acc.w, bb.w), 0.f);
    float z = h0 * ww.x + h1 * ww.y + h2 * ww.z + h3 * ww.w;
    z += __shfl_xor_sync(0xffffffffu, z, 1);
    z += __shfl_xor_sync(0xffffffffu, z, 2);
    if (c == 0) out[g] = 1.0f / (1.0f + expf(-(z + __ldg(bfc))));
}

extern "C" void kernel_launch(void* const* d_in, const int* in_sizes, int n_in,
                              void* d_out, int out_size) {
    const float* x   = (const float*)d_in[0];
    const int*   ei  = (const int*)d_in[1];
    const float* W1  = (const float*)d_in[2];
    const float* b1  = (const float*)d_in[3];
    const float* W2  = (const float*)d_in[4];
    const float* b2  = (const float*)d_in[5];
    const float* Wfc = (const float*)d_in[6];
    const float* bfc = (const float*)d_in[7];
    float* out = (float*)d_out;

    int n = in_sizes[0] / 8;   // nodes
    int e = in_sizes[1] / 2;   // edges
    const int* src = ei;
    const int* dst = ei + e;

    int gn = (n + NB - 1) / NB;
    int ge = (e + NB - 1) / NB;
    int g2n = ((n * 2) + NB - 1) / NB;   // 2 lanes/node (layer-1 gather)
    int g4n = ((n * 4) + NB - 1) / NB;   // 4 lanes/node (layer-2 gather)

    void* degp = nullptr;
    cudaGetSymbolAddress(&degp, g_degi);
    cudaMemsetAsync(degp, 0, (size_t)n * sizeof(int), 0);

    k_deg_slot<<<ge, NB>>>(dst, e);
    k_scan1<<<gn, NB>>>(n);
    k_scan3b<<<gn, NB>>>(x, n);
    k_fill2<<<ge, NB>>>(src, dst, e);
    k_gather1m<<<g2n, NB>>>(W1, b1, W2, n);
    k_gather2_final<<<g4n, NB>>>(b2, Wfc, bfc, out, n);
}